// round 1
// baseline (speedup 1.0000x reference)
#include <cuda_runtime.h>
#include <math.h>

// Problem geometry (fixed by the dataset)
#define N0c 1048576
#define N1c 65536
#define N2c 4096
#define DEG0c 16
#define DEG1c 10
#define DINc 128
#define DHc 256
#define DOUTc 47

// Scratch (alloc-free: __device__ globals)
__device__ float g_agg0[(size_t)N1c * DINc];   // 32 MB
__device__ float g_h0  [(size_t)N1c * DHc];    // 64 MB
__device__ float g_agg1[(size_t)N2c * DHc];    //  4 MB
__device__ float g_h1  [(size_t)N2c * DHc];    //  4 MB

__device__ __forceinline__ float gelu_exact(float v) {
    return 0.5f * v * (1.0f + erff(v * 0.7071067811865476f));
}

// ---------------------------------------------------------------------------
// Mean aggregation: one warp per dst node, float4 per lane per 128 cols.
// Fully unrolled neighbor loop -> high MLP, coalesced 512B row reads.
// ---------------------------------------------------------------------------
template<int D, int DEG>
__global__ void agg_kernel(const float* __restrict__ x, const int* __restrict__ idx,
                           float* __restrict__ out, int ndst)
{
    int warp = (blockIdx.x * blockDim.x + threadIdx.x) >> 5;
    int lane = threadIdx.x & 31;
    if (warp >= ndst) return;

    constexpr int C = D / 128;     // float4 chunks handled per lane
    float4 acc[C];
    #pragma unroll
    for (int c = 0; c < C; c++) acc[c] = make_float4(0.f, 0.f, 0.f, 0.f);

    const int* ep = idx + (size_t)warp * DEG;
    #pragma unroll
    for (int e = 0; e < DEG; e++) {
        int src = ep[e];
        const float4* row = (const float4*)(x + (size_t)src * D) + lane;
        #pragma unroll
        for (int c = 0; c < C; c++) {
            float4 v = row[32 * c];
            acc[c].x += v.x; acc[c].y += v.y; acc[c].z += v.z; acc[c].w += v.w;
        }
    }
    const float inv = 1.0f / (float)DEG;
    float4* o = (float4*)(out + (size_t)warp * D) + lane;
    #pragma unroll
    for (int c = 0; c < C; c++) {
        o[32 * c] = make_float4(acc[c].x * inv, acc[c].y * inv,
                                acc[c].z * inv, acc[c].w * inv);
    }
}

// ---------------------------------------------------------------------------
// Fused SAGE GEMM:  C[M,N] = [A1 | A2] @ [W1 | W2]^T + bias  (opt. exact GELU)
//   A1: [M,K1]  A2: [M,K2]   W1: [N,K1]  W2: [N,K2]  (row-major)
// Virtual concat along K -> no materialized concat buffer.
// Classic smem-tiled SGEMM, TMxTN register microtile.
// ---------------------------------------------------------------------------
template<int BM, int BN, int BK, int TM, int TN, bool GELU>
__global__ void __launch_bounds__((BM/TM)*(BN/TN))
gemm_kernel(const float* __restrict__ A1, const float* __restrict__ A2,
            int K1, int K2,
            const float* __restrict__ W1, const float* __restrict__ W2,
            const float* __restrict__ bias,
            float* __restrict__ C, int M, int N)
{
    constexpr int THREADS = (BM/TM)*(BN/TN);
    constexpr int VEC = 4;
    constexpr int KV = BK / VEC;                 // float4 groups per k-row
    constexpr int RPI = THREADS / KV;            // rows loaded per iteration

    __shared__ float As[BK][BM];
    __shared__ float Ws[BK][BN];

    const int K  = K1 + K2;
    const int m0 = blockIdx.x * BM;
    const int n0 = blockIdx.y * BN;
    const int tid = threadIdx.x;
    const int tx = tid % (BN/TN);
    const int ty = tid / (BN/TN);
    const int rr = tid / KV;
    const int cg = (tid % KV) * VEC;

    float acc[TM][TN];
    #pragma unroll
    for (int i = 0; i < TM; i++)
        #pragma unroll
        for (int j = 0; j < TN; j++) acc[i][j] = 0.f;

    for (int k0 = 0; k0 < K; k0 += BK) {
        const int gk = k0 + cg;   // 4-float group never straddles K1 (K1 % BK == 0)

        // A tile (store transposed: As[k][m])
        #pragma unroll
        for (int i = 0; i < BM; i += RPI) {
            int r = i + rr;
            const float* src = (gk < K1)
                ? (A1 + (size_t)(m0 + r) * K1 + gk)
                : (A2 + (size_t)(m0 + r) * K2 + (gk - K1));
            float4 v = *(const float4*)src;
            As[cg+0][r] = v.x; As[cg+1][r] = v.y; As[cg+2][r] = v.z; As[cg+3][r] = v.w;
        }
        // W tile (store transposed: Ws[k][n]); guard rows >= N (out-proj N=47)
        #pragma unroll
        for (int i = 0; i < BN; i += RPI) {
            int nr = i + rr;
            int n  = n0 + nr;
            float4 v = make_float4(0.f, 0.f, 0.f, 0.f);
            if (n < N) {
                const float* src = (gk < K1)
                    ? (W1 + (size_t)n * K1 + gk)
                    : (W2 + (size_t)n * K2 + (gk - K1));
                v = *(const float4*)src;
            }
            Ws[cg+0][nr] = v.x; Ws[cg+1][nr] = v.y; Ws[cg+2][nr] = v.z; Ws[cg+3][nr] = v.w;
        }
        __syncthreads();

        #pragma unroll
        for (int kk = 0; kk < BK; kk++) {
            float ra[TM], rb[TN];
            #pragma unroll
            for (int i = 0; i < TM; i += 4) {
                float4 t = *(const float4*)&As[kk][ty*TM + i];
                ra[i] = t.x; ra[i+1] = t.y; ra[i+2] = t.z; ra[i+3] = t.w;
            }
            #pragma unroll
            for (int j = 0; j < TN; j += 4) {
                float4 t = *(const float4*)&Ws[kk][tx*TN + j];
                rb[j] = t.x; rb[j+1] = t.y; rb[j+2] = t.z; rb[j+3] = t.w;
            }
            #pragma unroll
            for (int i = 0; i < TM; i++)
                #pragma unroll
                for (int j = 0; j < TN; j++)
                    acc[i][j] += ra[i] * rb[j];
        }
        __syncthreads();
    }

    // Epilogue: bias (+ exact GELU), bounds-guarded store (N may be 47)
    #pragma unroll
    for (int i = 0; i < TM; i++) {
        int m = m0 + ty*TM + i;
        #pragma unroll
        for (int j = 0; j < TN; j++) {
            int n = n0 + tx*TN + j;
            if (n < N) {
                float v = acc[i][j] + bias[n];
                if (GELU) v = gelu_exact(v);
                C[(size_t)m * N + n] = v;
            }
        }
    }
}

// ---------------------------------------------------------------------------
// Launch
// ---------------------------------------------------------------------------
extern "C" void kernel_launch(void* const* d_in, const int* in_sizes, int n_in,
                              void* d_out, int out_size)
{
    const float* x    = (const float*)d_in[0];
    const int*   idx0 = (const int*)  d_in[1];
    // d_in[2] = indptr0 (uniform degree 16, unused)
    const int*   idx1 = (const int*)  d_in[3];
    // d_in[4] = indptr1 (uniform degree 10, unused)
    const float* Wl0  = (const float*)d_in[5];
    const float* bl0  = (const float*)d_in[6];
    const float* Wr0  = (const float*)d_in[7];
    const float* Wl1  = (const float*)d_in[8];
    const float* bl1  = (const float*)d_in[9];
    const float* Wr1  = (const float*)d_in[10];
    const float* Wo   = (const float*)d_in[11];
    const float* bo   = (const float*)d_in[12];
    float* out = (float*)d_out;

    float *agg0, *h0, *agg1, *h1;
    cudaGetSymbolAddress((void**)&agg0, g_agg0);
    cudaGetSymbolAddress((void**)&h0,   g_h0);
    cudaGetSymbolAddress((void**)&agg1, g_agg1);
    cudaGetSymbolAddress((void**)&h1,   g_h1);

    // Layer 0: mean aggregation over 16 neighbors (D=128)
    agg_kernel<DINc, DEG0c><<<(N1c * 32) / 256, 256>>>(x, idx0, agg0, N1c);

    // Layer 0 GEMM: h0 = gelu([agg0 | x_dst] @ [Wl0|Wr0]^T + bl0)   [65536 x 256]
    gemm_kernel<128,128,16,8,8,true>
        <<<dim3(N1c/128, DHc/128), 256>>>(agg0, x, DINc, DINc,
                                          Wl0, Wr0, bl0, h0, N1c, DHc);

    // Layer 1: mean aggregation over 10 neighbors (D=256)
    agg_kernel<DHc, DEG1c><<<(N2c * 32) / 256, 256>>>(h0, idx1, agg1, N2c);

    // Layer 1 GEMM: h1 = gelu([agg1 | h0_dst] @ [Wl1|Wr1]^T + bl1)  [4096 x 256]
    gemm_kernel<64,64,16,4,4,true>
        <<<dim3(N2c/64, DHc/64), 256>>>(agg1, h0, DHc, DHc,
                                        Wl1, Wr1, bl1, h1, N2c, DHc);

    // Output projection: out = h1 @ Wo^T + bo   [4096 x 47]
    gemm_kernel<64,64,16,4,4,false>
        <<<dim3(N2c/64, 1), 256>>>(h1, h1, DHc, 0,
                                   Wo, Wo, bo, out, N2c, DOUTc);
}

// round 2
// speedup vs baseline: 1.9794x; 1.9794x over previous
#include <cuda_runtime.h>
#include <math.h>
#include <stdint.h>

// Problem geometry (fixed by the dataset)
#define N0c 1048576
#define N1c 65536
#define N2c 4096
#define DEG0c 16
#define DEG1c 10
#define DINc 128
#define DHc 256
#define DOUTc 47

// Scratch (alloc-free: __device__ globals)
__device__ float g_agg0[(size_t)N1c * DINc];   // 32 MB
__device__ float g_h0  [(size_t)N1c * DHc];    // 64 MB
__device__ float g_agg1[(size_t)N2c * DHc];    //  4 MB
__device__ float g_h1  [(size_t)N2c * DHc];    //  4 MB

__device__ __forceinline__ float gelu_exact(float v) {
    return 0.5f * v * (1.0f + erff(v * 0.7071067811865476f));
}

__device__ __forceinline__ uint32_t f2tf32(float f) {
    uint32_t u;
    asm("cvt.rna.tf32.f32 %0, %1;" : "=r"(u) : "f"(f));
    return u;
}

// ---------------------------------------------------------------------------
// Mean aggregation: one warp per dst node, float4 per lane per 128 cols.
// ---------------------------------------------------------------------------
template<int D, int DEG>
__global__ void agg_kernel(const float* __restrict__ x, const int* __restrict__ idx,
                           float* __restrict__ out, int ndst)
{
    int warp = (blockIdx.x * blockDim.x + threadIdx.x) >> 5;
    int lane = threadIdx.x & 31;
    if (warp >= ndst) return;

    constexpr int C = D / 128;     // float4 chunks handled per lane
    float4 acc[C];
    #pragma unroll
    for (int c = 0; c < C; c++) acc[c] = make_float4(0.f, 0.f, 0.f, 0.f);

    const int* ep = idx + (size_t)warp * DEG;
    #pragma unroll
    for (int e = 0; e < DEG; e++) {
        int src = ep[e];
        const float4* row = (const float4*)(x + (size_t)src * D) + lane;
        #pragma unroll
        for (int c = 0; c < C; c++) {
            float4 v = row[32 * c];
            acc[c].x += v.x; acc[c].y += v.y; acc[c].z += v.z; acc[c].w += v.w;
        }
    }
    const float inv = 1.0f / (float)DEG;
    float4* o = (float4*)(out + (size_t)warp * D) + lane;
    #pragma unroll
    for (int c = 0; c < C; c++) {
        o[32 * c] = make_float4(acc[c].x * inv, acc[c].y * inv,
                                acc[c].z * inv, acc[c].w * inv);
    }
}

// ---------------------------------------------------------------------------
// tf32 tensor-core GEMM:  C[M,N] = [A1|A2] @ [W1|W2]^T + bias (opt exact GELU)
//   A1:[M,K1] A2:[M,K2] W1:[N,K1] W2:[N,K2], all row-major fp32.
// CTA tile 128x128, BK=32, 8 warps (2x4) of 64x32 warp tiles.
// mma.sync.m16n8k8.tf32, fragments via ldmatrix from padded (36-float-row)
// smem tiles -> conflict-free, no smem transpose.
// ---------------------------------------------------------------------------
template<bool GELU>
__global__ void __launch_bounds__(256, 1)
mma_gemm(const float* __restrict__ A1, const float* __restrict__ A2,
         int K1, int K2,
         const float* __restrict__ W1, const float* __restrict__ W2,
         const float* __restrict__ bias,
         float* __restrict__ C, int M, int N)
{
    constexpr int BM = 128, BN = 128, BK = 32, SA = 36;
    extern __shared__ uint32_t sm[];
    uint32_t* As = sm;                 // [2][BM*SA]
    uint32_t* Ws = sm + 2 * BM * SA;   // [2][BN*SA]

    const int K  = K1 + K2;
    const int m0 = blockIdx.x * BM;
    const int n0 = blockIdx.y * BN;
    const int tid  = threadIdx.x;
    const int lane = tid & 31;
    const int warp = tid >> 5;
    const int warpM = warp >> 2;       // 0..1
    const int warpN = warp & 3;        // 0..3
    const int lrow = tid >> 3;         // 0..31
    const int lcol = (tid & 7) * 4;    // 0,4,...,28

    // ---- global fetch (register prefetch) ----
    float4 pa[4], pb[4];
    auto fetch = [&](int k0) {
        const int gk = k0 + lcol;      // whole float4 stays on one side (K1 % BK == 0)
        #pragma unroll
        for (int p = 0; p < 4; p++) {
            const int r = lrow + p * 32;
            const int m = m0 + r;
            const float* srcA = (gk < K1)
                ? A1 + (size_t)m * K1 + gk
                : A2 + (size_t)m * K2 + (gk - K1);
            pa[p] = *(const float4*)srcA;
            const int n = n0 + r;
            if (n < N) {
                const float* srcW = (gk < K1)
                    ? W1 + (size_t)n * K1 + gk
                    : W2 + (size_t)n * K2 + (gk - K1);
                pb[p] = *(const float4*)srcW;
            } else {
                pb[p] = make_float4(0.f, 0.f, 0.f, 0.f);
            }
        }
    };
    auto stage = [&](int buf) {
        #pragma unroll
        for (int p = 0; p < 4; p++) {
            const int r = lrow + p * 32;
            uint32_t* da = As + buf * BM * SA + r * SA + lcol;
            da[0] = f2tf32(pa[p].x); da[1] = f2tf32(pa[p].y);
            da[2] = f2tf32(pa[p].z); da[3] = f2tf32(pa[p].w);
            uint32_t* dw = Ws + buf * BM * SA + r * SA + lcol;
            dw[0] = f2tf32(pb[p].x); dw[1] = f2tf32(pb[p].y);
            dw[2] = f2tf32(pb[p].z); dw[3] = f2tf32(pb[p].w);
        }
    };

    float acc[4][4][4] = {};

    // ldmatrix lane-address geometry
    const int quad = lane >> 3, qr = lane & 7;
    const int aRowB = warpM * 64 + (quad & 1) * 8 + qr;  // + mi*16
    const int aColB = (quad >> 1) * 4;                   // + ks*8
    const int bq = (lane & 15) >> 3, br = lane & 7;
    const int bRowB = warpN * 32 + br;                   // + ni*8
    const int bColB = bq * 4;                            // + ks*8

    const uint32_t smA = (uint32_t)__cvta_generic_to_shared(As);
    const uint32_t smW = (uint32_t)__cvta_generic_to_shared(Ws);

    fetch(0);
    stage(0);
    __syncthreads();

    int buf = 0;
    const int nk = K / BK;
    for (int it = 0; it < nk; it++) {
        if (it + 1 < nk) fetch((it + 1) * BK);

        const uint32_t baseA = smA + (uint32_t)(buf * BM * SA) * 4u;
        const uint32_t baseW = smW + (uint32_t)(buf * BM * SA) * 4u;

        #pragma unroll
        for (int ks = 0; ks < BK / 8; ks++) {
            uint32_t a[4][4], b[4][2];
            #pragma unroll
            for (int mi = 0; mi < 4; mi++) {
                uint32_t ad = baseA + (uint32_t)(((aRowB + mi * 16) * SA) + ks * 8 + aColB) * 4u;
                asm volatile("ldmatrix.sync.aligned.m8n8.x4.shared.b16 {%0,%1,%2,%3}, [%4];\n"
                             : "=r"(a[mi][0]), "=r"(a[mi][1]), "=r"(a[mi][2]), "=r"(a[mi][3])
                             : "r"(ad));
            }
            #pragma unroll
            for (int ni = 0; ni < 4; ni++) {
                uint32_t bd = baseW + (uint32_t)(((bRowB + ni * 8) * SA) + ks * 8 + bColB) * 4u;
                asm volatile("ldmatrix.sync.aligned.m8n8.x2.shared.b16 {%0,%1}, [%2];\n"
                             : "=r"(b[ni][0]), "=r"(b[ni][1])
                             : "r"(bd));
            }
            #pragma unroll
            for (int mi = 0; mi < 4; mi++)
                #pragma unroll
                for (int ni = 0; ni < 4; ni++) {
                    asm volatile(
                        "mma.sync.aligned.m16n8k8.row.col.f32.tf32.tf32.f32 "
                        "{%0,%1,%2,%3}, {%4,%5,%6,%7}, {%8,%9}, {%0,%1,%2,%3};\n"
                        : "+f"(acc[mi][ni][0]), "+f"(acc[mi][ni][1]),
                          "+f"(acc[mi][ni][2]), "+f"(acc[mi][ni][3])
                        : "r"(a[mi][0]), "r"(a[mi][1]), "r"(a[mi][2]), "r"(a[mi][3]),
                          "r"(b[ni][0]), "r"(b[ni][1]));
                }
        }

        if (it + 1 < nk) stage(buf ^ 1);
        __syncthreads();
        buf ^= 1;
    }

    // ---- epilogue: bias (+GELU), guarded stores ----
    const int g = lane >> 2, l = lane & 3;
    #pragma unroll
    for (int mi = 0; mi < 4; mi++) {
        #pragma unroll
        for (int ni = 0; ni < 4; ni++) {
            const int m = m0 + warpM * 64 + mi * 16 + g;
            const int n = n0 + warpN * 32 + ni * 8 + 2 * l;
            float* c = acc[mi][ni];
            if (n < N) {
                float v0 = c[0] + bias[n];
                float v2 = c[2] + bias[n];
                if (GELU) { v0 = gelu_exact(v0); v2 = gelu_exact(v2); }
                C[(size_t)m * N + n]       = v0;
                C[(size_t)(m + 8) * N + n] = v2;
            }
            if (n + 1 < N) {
                float v1 = c[1] + bias[n + 1];
                float v3 = c[3] + bias[n + 1];
                if (GELU) { v1 = gelu_exact(v1); v3 = gelu_exact(v3); }
                C[(size_t)m * N + n + 1]       = v1;
                C[(size_t)(m + 8) * N + n + 1] = v3;
            }
        }
    }
}

// ---------------------------------------------------------------------------
// Launch
// ---------------------------------------------------------------------------
extern "C" void kernel_launch(void* const* d_in, const int* in_sizes, int n_in,
                              void* d_out, int out_size)
{
    const float* x    = (const float*)d_in[0];
    const int*   idx0 = (const int*)  d_in[1];
    const int*   idx1 = (const int*)  d_in[3];
    const float* Wl0  = (const float*)d_in[5];
    const float* bl0  = (const float*)d_in[6];
    const float* Wr0  = (const float*)d_in[7];
    const float* Wl1  = (const float*)d_in[8];
    const float* bl1  = (const float*)d_in[9];
    const float* Wr1  = (const float*)d_in[10];
    const float* Wo   = (const float*)d_in[11];
    const float* bo   = (const float*)d_in[12];
    float* out = (float*)d_out;

    float *agg0, *h0, *agg1, *h1;
    cudaGetSymbolAddress((void**)&agg0, g_agg0);
    cudaGetSymbolAddress((void**)&h0,   g_h0);
    cudaGetSymbolAddress((void**)&agg1, g_agg1);
    cudaGetSymbolAddress((void**)&h1,   g_h1);

    const int SMEM = 4 * 128 * 36 * 4;   // 73728 B (double-buffered A+W tiles)
    cudaFuncSetAttribute(mma_gemm<true>,  cudaFuncAttributeMaxDynamicSharedMemorySize, SMEM);
    cudaFuncSetAttribute(mma_gemm<false>, cudaFuncAttributeMaxDynamicSharedMemorySize, SMEM);

    // Layer 0: mean aggregation over 16 neighbors (D=128)
    agg_kernel<DINc, DEG0c><<<(N1c * 32) / 256, 256>>>(x, idx0, agg0, N1c);

    // Layer 0 GEMM: h0 = gelu([agg0 | x_dst] @ [Wl0|Wr0]^T + bl0)   [65536 x 256]
    mma_gemm<true><<<dim3(N1c / 128, DHc / 128), 256, SMEM>>>(
        agg0, x, DINc, DINc, Wl0, Wr0, bl0, h0, N1c, DHc);

    // Layer 1: mean aggregation over 10 neighbors (D=256)
    agg_kernel<DHc, DEG1c><<<(N2c * 32) / 256, 256>>>(h0, idx1, agg1, N2c);

    // Layer 1 GEMM: h1 = gelu([agg1 | h0_dst] @ [Wl1|Wr1]^T + bl1)  [4096 x 256]
    mma_gemm<true><<<dim3(N2c / 128, DHc / 128), 256, SMEM>>>(
        agg1, h0, DHc, DHc, Wl1, Wr1, bl1, h1, N2c, DHc);

    // Output projection: out = h1 @ Wo^T + bo   [4096 x 47]
    mma_gemm<false><<<dim3(N2c / 128, 1), 256, SMEM>>>(
        h1, h1, DHc, 0, Wo, Wo, bo, out, N2c, DOUTc);
}

// round 3
// speedup vs baseline: 2.0518x; 1.0366x over previous
#include <cuda_runtime.h>
#include <math.h>
#include <stdint.h>

// Problem geometry (fixed by the dataset)
#define N0c 1048576
#define N1c 65536
#define N2c 4096
#define DEG0c 16
#define DEG1c 10
#define DINc 128
#define DHc 256
#define DOUTc 47

// Scratch (alloc-free: __device__ globals)
__device__ float g_agg0[(size_t)N1c * DINc];   // 32 MB
__device__ float g_h0  [(size_t)N1c * DHc];    // 64 MB
__device__ float g_agg1[(size_t)N2c * DHc];    //  4 MB
__device__ float g_h1  [(size_t)N2c * DHc];    //  4 MB

__device__ __forceinline__ float gelu_exact(float v) {
    return 0.5f * v * (1.0f + erff(v * 0.7071067811865476f));
}

__device__ __forceinline__ uint32_t f2tf32(float f) {
    uint32_t u;
    asm("cvt.rna.tf32.f32 %0, %1;" : "=r"(u) : "f"(f));
    return u;
}

__device__ __forceinline__ void cp16(uint32_t saddr, const void* gaddr) {
    asm volatile("cp.async.cg.shared.global [%0], [%1], 16;\n" :: "r"(saddr), "l"(gaddr));
}

// ---------------------------------------------------------------------------
// Mean aggregation, cp.async-staged:
// each block gathers NDST*DEG rows of D floats into smem via 16B cp.async
// (deep, register-free pipeline), then warps reduce and store the mean.
// ---------------------------------------------------------------------------
template<int D, int DEG, int NDST>
__global__ void __launch_bounds__(256)
agg_cp_kernel(const float* __restrict__ x, const int* __restrict__ idx,
              float* __restrict__ out)
{
    constexpr int C4   = D / 4;               // float4 per row
    constexpr int NCHK = NDST * DEG * C4;     // total float4 chunks per block
    constexpr int PER  = NCHK / 256;          // chunks per thread

    extern __shared__ float4 sbuf[];          // [NDST*DEG][C4]
    const uint32_t sbase = (uint32_t)__cvta_generic_to_shared(sbuf);

    const int tid = threadIdx.x;
    const int dst0 = blockIdx.x * NDST;
    const int ebase = dst0 * DEG;

    #pragma unroll
    for (int p = 0; p < PER; p++) {
        const int c = tid + p * 256;
        const int eg  = c / C4;               // (dst_local, edge) flattened
        const int col = c % C4;
        const int src = idx[ebase + eg];
        cp16(sbase + (uint32_t)c * 16u, x + (size_t)src * D + col * 4);
    }
    asm volatile("cp.async.commit_group;\n" ::);
    asm volatile("cp.async.wait_group 0;\n" ::);
    __syncthreads();

    // Reduce: warps split (dst, column-half) work.
    constexpr int WPD = 8 / NDST;             // warps per dst (1 for D=128, 2 for D=256)
    const int warp = tid >> 5, lane = tid & 31;
    const int dl   = warp / WPD;              // dst local
    const int half = warp % WPD;
    const int col  = half * 32 + lane;        // float4 column (col < C4 guaranteed)

    float4 acc = make_float4(0.f, 0.f, 0.f, 0.f);
    #pragma unroll
    for (int e = 0; e < DEG; e++) {
        float4 v = sbuf[(dl * DEG + e) * C4 + col];
        acc.x += v.x; acc.y += v.y; acc.z += v.z; acc.w += v.w;
    }
    const float inv = 1.0f / (float)DEG;
    ((float4*)(out + (size_t)(dst0 + dl) * D))[col] =
        make_float4(acc.x * inv, acc.y * inv, acc.z * inv, acc.w * inv);
}

// ---------------------------------------------------------------------------
// tf32 tensor-core GEMM (128x128 CTA tile, 8 warps of 64x32):
//   C[M,N] = [A1|A2] @ [W1|W2]^T + bias  (opt exact GELU)
// ---------------------------------------------------------------------------
template<bool GELU>
__global__ void __launch_bounds__(256, 1)
mma_gemm(const float* __restrict__ A1, const float* __restrict__ A2,
         int K1, int K2,
         const float* __restrict__ W1, const float* __restrict__ W2,
         const float* __restrict__ bias,
         float* __restrict__ C, int M, int N)
{
    constexpr int BM = 128, BK = 32, SA = 36;
    extern __shared__ uint32_t sm[];
    uint32_t* As = sm;
    uint32_t* Ws = sm + 2 * BM * SA;

    const int K  = K1 + K2;
    const int m0 = blockIdx.x * BM;
    const int n0 = blockIdx.y * BM;
    const int tid  = threadIdx.x;
    const int lane = tid & 31;
    const int warp = tid >> 5;
    const int warpM = warp >> 2;
    const int warpN = warp & 3;
    const int lrow = tid >> 3;
    const int lcol = (tid & 7) * 4;

    float4 pa[4], pb[4];
    auto fetch = [&](int k0) {
        const int gk = k0 + lcol;
        #pragma unroll
        for (int p = 0; p < 4; p++) {
            const int r = lrow + p * 32;
            const int m = m0 + r;
            const float* srcA = (gk < K1)
                ? A1 + (size_t)m * K1 + gk
                : A2 + (size_t)m * K2 + (gk - K1);
            pa[p] = *(const float4*)srcA;
            const int n = n0 + r;
            if (n < N) {
                const float* srcW = (gk < K1)
                    ? W1 + (size_t)n * K1 + gk
                    : W2 + (size_t)n * K2 + (gk - K1);
                pb[p] = *(const float4*)srcW;
            } else {
                pb[p] = make_float4(0.f, 0.f, 0.f, 0.f);
            }
        }
    };
    auto stage = [&](int buf) {
        #pragma unroll
        for (int p = 0; p < 4; p++) {
            const int r = lrow + p * 32;
            uint32_t* da = As + buf * BM * SA + r * SA + lcol;
            da[0] = f2tf32(pa[p].x); da[1] = f2tf32(pa[p].y);
            da[2] = f2tf32(pa[p].z); da[3] = f2tf32(pa[p].w);
            uint32_t* dw = Ws + buf * BM * SA + r * SA + lcol;
            dw[0] = f2tf32(pb[p].x); dw[1] = f2tf32(pb[p].y);
            dw[2] = f2tf32(pb[p].z); dw[3] = f2tf32(pb[p].w);
        }
    };

    float acc[4][4][4] = {};

    const int quad = lane >> 3, qr = lane & 7;
    const int aRowB = warpM * 64 + (quad & 1) * 8 + qr;
    const int aColB = (quad >> 1) * 4;
    const int bq = (lane & 15) >> 3, br = lane & 7;
    const int bRowB = warpN * 32 + br;
    const int bColB = bq * 4;

    const uint32_t smA = (uint32_t)__cvta_generic_to_shared(As);
    const uint32_t smW = (uint32_t)__cvta_generic_to_shared(Ws);

    fetch(0);
    stage(0);
    __syncthreads();

    int buf = 0;
    const int nk = K / BK;
    for (int it = 0; it < nk; it++) {
        if (it + 1 < nk) fetch((it + 1) * BK);

        const uint32_t baseA = smA + (uint32_t)(buf * BM * SA) * 4u;
        const uint32_t baseW = smW + (uint32_t)(buf * BM * SA) * 4u;

        #pragma unroll
        for (int ks = 0; ks < BK / 8; ks++) {
            uint32_t a[4][4], b[4][2];
            #pragma unroll
            for (int mi = 0; mi < 4; mi++) {
                uint32_t ad = baseA + (uint32_t)(((aRowB + mi * 16) * SA) + ks * 8 + aColB) * 4u;
                asm volatile("ldmatrix.sync.aligned.m8n8.x4.shared.b16 {%0,%1,%2,%3}, [%4];\n"
                             : "=r"(a[mi][0]), "=r"(a[mi][1]), "=r"(a[mi][2]), "=r"(a[mi][3])
                             : "r"(ad));
            }
            #pragma unroll
            for (int ni = 0; ni < 4; ni++) {
                uint32_t bd = baseW + (uint32_t)(((bRowB + ni * 8) * SA) + ks * 8 + bColB) * 4u;
                asm volatile("ldmatrix.sync.aligned.m8n8.x2.shared.b16 {%0,%1}, [%2];\n"
                             : "=r"(b[ni][0]), "=r"(b[ni][1])
                             : "r"(bd));
            }
            #pragma unroll
            for (int mi = 0; mi < 4; mi++)
                #pragma unroll
                for (int ni = 0; ni < 4; ni++) {
                    asm volatile(
                        "mma.sync.aligned.m16n8k8.row.col.f32.tf32.tf32.f32 "
                        "{%0,%1,%2,%3}, {%4,%5,%6,%7}, {%8,%9}, {%0,%1,%2,%3};\n"
                        : "+f"(acc[mi][ni][0]), "+f"(acc[mi][ni][1]),
                          "+f"(acc[mi][ni][2]), "+f"(acc[mi][ni][3])
                        : "r"(a[mi][0]), "r"(a[mi][1]), "r"(a[mi][2]), "r"(a[mi][3]),
                          "r"(b[ni][0]), "r"(b[ni][1]));
                }
        }

        if (it + 1 < nk) stage(buf ^ 1);
        __syncthreads();
        buf ^= 1;
    }

    const int g = lane >> 2, l = lane & 3;
    #pragma unroll
    for (int mi = 0; mi < 4; mi++) {
        #pragma unroll
        for (int ni = 0; ni < 4; ni++) {
            const int m = m0 + warpM * 64 + mi * 16 + g;
            const int n = n0 + warpN * 32 + ni * 8 + 2 * l;
            float* c = acc[mi][ni];
            if (n < N) {
                float v0 = c[0] + bias[n];
                float v2 = c[2] + bias[n];
                if (GELU) { v0 = gelu_exact(v0); v2 = gelu_exact(v2); }
                C[(size_t)m * N + n]       = v0;
                C[(size_t)(m + 8) * N + n] = v2;
            }
            if (n + 1 < N) {
                float v1 = c[1] + bias[n + 1];
                float v3 = c[3] + bias[n + 1];
                if (GELU) { v1 = gelu_exact(v1); v3 = gelu_exact(v3); }
                C[(size_t)m * N + n + 1]       = v1;
                C[(size_t)(m + 8) * N + n + 1] = v3;
            }
        }
    }
}

// ---------------------------------------------------------------------------
// 64x64 CTA-tile variant (4 warps of 32x32) for the small GEMMs.
// ---------------------------------------------------------------------------
template<bool GELU>
__global__ void __launch_bounds__(128, 1)
mma_gemm64(const float* __restrict__ A1, const float* __restrict__ A2,
           int K1, int K2,
           const float* __restrict__ W1, const float* __restrict__ W2,
           const float* __restrict__ bias,
           float* __restrict__ C, int M, int N)
{
    constexpr int BM = 64, BK = 32, SA = 36;
    extern __shared__ uint32_t sm[];
    uint32_t* As = sm;
    uint32_t* Ws = sm + 2 * BM * SA;

    const int K  = K1 + K2;
    const int m0 = blockIdx.x * BM;
    const int n0 = blockIdx.y * BM;
    const int tid  = threadIdx.x;
    const int lane = tid & 31;
    const int warp = tid >> 5;
    const int warpM = warp >> 1;        // 0..1
    const int warpN = warp & 1;         // 0..1
    const int lrow = tid >> 3;          // 0..15
    const int lcol = (tid & 7) * 4;

    float4 pa[4], pb[4];
    auto fetch = [&](int k0) {
        const int gk = k0 + lcol;
        #pragma unroll
        for (int p = 0; p < 4; p++) {
            const int r = lrow + p * 16;
            const int m = m0 + r;
            const float* srcA = (gk < K1)
                ? A1 + (size_t)m * K1 + gk
                : A2 + (size_t)m * K2 + (gk - K1);
            pa[p] = *(const float4*)srcA;
            const int n = n0 + r;
            if (n < N) {
                const float* srcW = (gk < K1)
                    ? W1 + (size_t)n * K1 + gk
                    : W2 + (size_t)n * K2 + (gk - K1);
                pb[p] = *(const float4*)srcW;
            } else {
                pb[p] = make_float4(0.f, 0.f, 0.f, 0.f);
            }
        }
    };
    auto stage = [&](int buf) {
        #pragma unroll
        for (int p = 0; p < 4; p++) {
            const int r = lrow + p * 16;
            uint32_t* da = As + buf * BM * SA + r * SA + lcol;
            da[0] = f2tf32(pa[p].x); da[1] = f2tf32(pa[p].y);
            da[2] = f2tf32(pa[p].z); da[3] = f2tf32(pa[p].w);
            uint32_t* dw = Ws + buf * BM * SA + r * SA + lcol;
            dw[0] = f2tf32(pb[p].x); dw[1] = f2tf32(pb[p].y);
            dw[2] = f2tf32(pb[p].z); dw[3] = f2tf32(pb[p].w);
        }
    };

    float acc[2][4][4] = {};

    const int quad = lane >> 3, qr = lane & 7;
    const int aRowB = warpM * 32 + (quad & 1) * 8 + qr;
    const int aColB = (quad >> 1) * 4;
    const int bq = (lane & 15) >> 3, br = lane & 7;
    const int bRowB = warpN * 32 + br;
    const int bColB = bq * 4;

    const uint32_t smA = (uint32_t)__cvta_generic_to_shared(As);
    const uint32_t smW = (uint32_t)__cvta_generic_to_shared(Ws);

    fetch(0);
    stage(0);
    __syncthreads();

    int buf = 0;
    const int nk = K / BK;
    for (int it = 0; it < nk; it++) {
        if (it + 1 < nk) fetch((it + 1) * BK);

        const uint32_t baseA = smA + (uint32_t)(buf * BM * SA) * 4u;
        const uint32_t baseW = smW + (uint32_t)(buf * BM * SA) * 4u;

        #pragma unroll
        for (int ks = 0; ks < BK / 8; ks++) {
            uint32_t a[2][4], b[4][2];
            #pragma unroll
            for (int mi = 0; mi < 2; mi++) {
                uint32_t ad = baseA + (uint32_t)(((aRowB + mi * 16) * SA) + ks * 8 + aColB) * 4u;
                asm volatile("ldmatrix.sync.aligned.m8n8.x4.shared.b16 {%0,%1,%2,%3}, [%4];\n"
                             : "=r"(a[mi][0]), "=r"(a[mi][1]), "=r"(a[mi][2]), "=r"(a[mi][3])
                             : "r"(ad));
            }
            #pragma unroll
            for (int ni = 0; ni < 4; ni++) {
                uint32_t bd = baseW + (uint32_t)(((bRowB + ni * 8) * SA) + ks * 8 + bColB) * 4u;
                asm volatile("ldmatrix.sync.aligned.m8n8.x2.shared.b16 {%0,%1}, [%2];\n"
                             : "=r"(b[ni][0]), "=r"(b[ni][1])
                             : "r"(bd));
            }
            #pragma unroll
            for (int mi = 0; mi < 2; mi++)
                #pragma unroll
                for (int ni = 0; ni < 4; ni++) {
                    asm volatile(
                        "mma.sync.aligned.m16n8k8.row.col.f32.tf32.tf32.f32 "
                        "{%0,%1,%2,%3}, {%4,%5,%6,%7}, {%8,%9}, {%0,%1,%2,%3};\n"
                        : "+f"(acc[mi][ni][0]), "+f"(acc[mi][ni][1]),
                          "+f"(acc[mi][ni][2]), "+f"(acc[mi][ni][3])
                        : "r"(a[mi][0]), "r"(a[mi][1]), "r"(a[mi][2]), "r"(a[mi][3]),
                          "r"(b[ni][0]), "r"(b[ni][1]));
                }
        }

        if (it + 1 < nk) stage(buf ^ 1);
        __syncthreads();
        buf ^= 1;
    }

    const int g = lane >> 2, l = lane & 3;
    #pragma unroll
    for (int mi = 0; mi < 2; mi++) {
        #pragma unroll
        for (int ni = 0; ni < 4; ni++) {
            const int m = m0 + warpM * 32 + mi * 16 + g;
            const int n = n0 + warpN * 32 + ni * 8 + 2 * l;
            float* c = acc[mi][ni];
            if (n < N) {
                float v0 = c[0] + bias[n];
                float v2 = c[2] + bias[n];
                if (GELU) { v0 = gelu_exact(v0); v2 = gelu_exact(v2); }
                C[(size_t)m * N + n]       = v0;
                C[(size_t)(m + 8) * N + n] = v2;
            }
            if (n + 1 < N) {
                float v1 = c[1] + bias[n + 1];
                float v3 = c[3] + bias[n + 1];
                if (GELU) { v1 = gelu_exact(v1); v3 = gelu_exact(v3); }
                C[(size_t)m * N + n + 1]       = v1;
                C[(size_t)(m + 8) * N + n + 1] = v3;
            }
        }
    }
}

// ---------------------------------------------------------------------------
// Launch
// ---------------------------------------------------------------------------
extern "C" void kernel_launch(void* const* d_in, const int* in_sizes, int n_in,
                              void* d_out, int out_size)
{
    const float* x    = (const float*)d_in[0];
    const int*   idx0 = (const int*)  d_in[1];
    const int*   idx1 = (const int*)  d_in[3];
    const float* Wl0  = (const float*)d_in[5];
    const float* bl0  = (const float*)d_in[6];
    const float* Wr0  = (const float*)d_in[7];
    const float* Wl1  = (const float*)d_in[8];
    const float* bl1  = (const float*)d_in[9];
    const float* Wr1  = (const float*)d_in[10];
    const float* Wo   = (const float*)d_in[11];
    const float* bo   = (const float*)d_in[12];
    float* out = (float*)d_out;

    float *agg0, *h0, *agg1, *h1;
    cudaGetSymbolAddress((void**)&agg0, g_agg0);
    cudaGetSymbolAddress((void**)&h0,   g_h0);
    cudaGetSymbolAddress((void**)&agg1, g_agg1);
    cudaGetSymbolAddress((void**)&h1,   g_h1);

    const int SMEM_G128 = 4 * 128 * 36 * 4;          // 73728 B
    const int SMEM_G64  = 4 * 64 * 36 * 4;           // 36864 B
    const int SMEM_A0   = 8 * DEG0c * DINc * 4;      // 65536 B
    const int SMEM_A1   = 4 * DEG1c * DHc * 4;       // 40960 B
    cudaFuncSetAttribute(mma_gemm<true>,    cudaFuncAttributeMaxDynamicSharedMemorySize, SMEM_G128);
    cudaFuncSetAttribute(mma_gemm64<true>,  cudaFuncAttributeMaxDynamicSharedMemorySize, SMEM_G64);
    cudaFuncSetAttribute(mma_gemm64<false>, cudaFuncAttributeMaxDynamicSharedMemorySize, SMEM_G64);
    cudaFuncSetAttribute(agg_cp_kernel<DINc, DEG0c, 8>, cudaFuncAttributeMaxDynamicSharedMemorySize, SMEM_A0);
    cudaFuncSetAttribute(agg_cp_kernel<DHc,  DEG1c, 4>, cudaFuncAttributeMaxDynamicSharedMemorySize, SMEM_A1);

    // Layer 0: mean aggregation over 16 neighbors (D=128), cp.async staged
    agg_cp_kernel<DINc, DEG0c, 8><<<N1c / 8, 256, SMEM_A0>>>(x, idx0, agg0);

    // Layer 0 GEMM: h0 = gelu([agg0 | x_dst] @ [Wl0|Wr0]^T + bl0)   [65536 x 256]
    mma_gemm<true><<<dim3(N1c / 128, DHc / 128), 256, SMEM_G128>>>(
        agg0, x, DINc, DINc, Wl0, Wr0, bl0, h0, N1c, DHc);

    // Layer 1: mean aggregation over 10 neighbors (D=256)
    agg_cp_kernel<DHc, DEG1c, 4><<<N2c / 4, 256, SMEM_A1>>>(h0, idx1, agg1);

    // Layer 1 GEMM: h1 = gelu([agg1 | h0_dst] @ [Wl1|Wr1]^T + bl1)  [4096 x 256]
    mma_gemm64<true><<<dim3(N2c / 64, DHc / 64), 128, SMEM_G64>>>(
        agg1, h0, DHc, DHc, Wl1, Wr1, bl1, h1, N2c, DHc);

    // Output projection: out = h1 @ Wo^T + bo   [4096 x 47]
    mma_gemm64<false><<<dim3(N2c / 64, 1), 128, SMEM_G64>>>(
        h1, h1, DHc, 0, Wo, Wo, bo, out, N2c, DOUTc);
}

// round 4
// speedup vs baseline: 2.9870x; 1.4558x over previous
#include <cuda_runtime.h>
#include <math.h>
#include <stdint.h>

// Problem geometry (fixed by the dataset)
#define N0c 1048576
#define N1c 65536
#define N2c 4096
#define DEG0c 16
#define DEG1c 10
#define DINc 128
#define DHc 256
#define DOUTc 47
#define E1c (N2c * DEG1c)

// Scratch (alloc-free: __device__ globals)
__device__ float g_agg0[(size_t)N1c * DINc];   // 32 MB (compact rows)
__device__ float g_h0  [(size_t)N1c * DHc];    // 64 MB (compact rows)
__device__ float g_agg1[(size_t)N2c * DHc];    //  4 MB
__device__ float g_h1  [(size_t)N2c * DHc];    //  4 MB
__device__ int   g_mask [N1c];
__device__ int   g_list [N1c];                 // compact row -> node id
__device__ int   g_remap[N1c];                 // node id -> compact row
__device__ int   g_cnt;

__device__ __forceinline__ float gelu_exact(float v) {
    return 0.5f * v * (1.0f + erff(v * 0.7071067811865476f));
}

__device__ __forceinline__ uint32_t f2tf32(float f) {
    uint32_t u;
    asm("cvt.rna.tf32.f32 %0, %1;" : "=r"(u) : "f"(f));
    return u;
}

__device__ __forceinline__ void cp16(uint32_t saddr, const void* gaddr) {
    asm volatile("cp.async.cg.shared.global [%0], [%1], 16;\n" :: "r"(saddr), "l"(gaddr));
}

// ---------------------------------------------------------------------------
// Dedup pipeline: mark nodes needed by layer 1 (edge srcs + seeds), compact.
// ---------------------------------------------------------------------------
__global__ void init_kernel(int* mask, int* list, int* cnt)
{
    int t = blockIdx.x * blockDim.x + threadIdx.x;
    mask[t] = (t < N2c) ? 1 : 0;   // seeds always needed (self term of layer 1)
    list[t] = 0;                    // padding rows alias node 0 (valid memory)
    if (t == 0) *cnt = 0;
}

__global__ void mark_kernel(const int* __restrict__ idx1, int* mask)
{
    int t = blockIdx.x * blockDim.x + threadIdx.x;
    if (t < E1c) mask[idx1[t]] = 1;
}

__global__ void compact_kernel(const int* __restrict__ mask, int* list,
                               int* remap, int* cnt)
{
    int n = blockIdx.x * blockDim.x + threadIdx.x;
    if (n < N1c && mask[n]) {
        int p = atomicAdd(cnt, 1);
        list[p] = n;
        remap[n] = p;
    }
}

// ---------------------------------------------------------------------------
// Mean aggregation, cp.async-staged, with optional dst-list / src-remap.
// Each block gathers NDST*DEG rows of D floats into smem via 16B cp.async,
// then warps reduce and store the mean (to compact row dst0+dl).
// ---------------------------------------------------------------------------
template<int D, int DEG, int NDST, bool DLIST, bool SRCMAP>
__global__ void __launch_bounds__(256)
agg_cp_kernel(const float* __restrict__ x, const int* __restrict__ idx,
              float* __restrict__ out,
              const int* __restrict__ dlist, const int* __restrict__ srcmap,
              const int* __restrict__ cntp)
{
    constexpr int C4   = D / 4;
    constexpr int NCHK = NDST * DEG * C4;
    constexpr int PER  = NCHK / 256;

    const int dst0 = blockIdx.x * NDST;
    if (DLIST) {
        const int cnt_pad = (*cntp + 127) & ~127;
        if (dst0 >= cnt_pad) return;
    }

    extern __shared__ float4 sbuf[];          // [NDST*DEG][C4]
    const uint32_t sbase = (uint32_t)__cvta_generic_to_shared(sbuf);
    const int tid = threadIdx.x;

    #pragma unroll
    for (int p = 0; p < PER; p++) {
        const int c   = tid + p * 256;
        const int eg  = c / C4;
        const int col = c % C4;
        const int dl  = eg / DEG;
        const int e   = eg % DEG;
        const int node = DLIST ? dlist[dst0 + dl] : (dst0 + dl);
        int src = idx[(size_t)node * DEG + e];
        if (SRCMAP) src = srcmap[src];
        cp16(sbase + (uint32_t)c * 16u, x + (size_t)src * D + col * 4);
    }
    asm volatile("cp.async.commit_group;\n" ::);
    asm volatile("cp.async.wait_group 0;\n" ::);
    __syncthreads();

    constexpr int WPD = 8 / NDST;
    const int warp = tid >> 5, lane = tid & 31;
    const int dl   = warp / WPD;
    const int half = warp % WPD;
    const int col  = half * 32 + lane;

    float4 acc = make_float4(0.f, 0.f, 0.f, 0.f);
    #pragma unroll
    for (int e = 0; e < DEG; e++) {
        float4 v = sbuf[(dl * DEG + e) * C4 + col];
        acc.x += v.x; acc.y += v.y; acc.z += v.z; acc.w += v.w;
    }
    const float inv = 1.0f / (float)DEG;
    ((float4*)(out + (size_t)(dst0 + dl) * D))[col] =
        make_float4(acc.x * inv, acc.y * inv, acc.z * inv, acc.w * inv);
}

// ---------------------------------------------------------------------------
// tf32 tensor-core GEMM (128x128 CTA tile, 8 warps of 64x32):
//   C[M,N] = [A1|A2g] @ [W1|W2]^T + bias  (opt exact GELU)
// A2 rows optionally gathered via rowA2[m]; CTA count optionally bounded by
// device counter (padded to 128).
// ---------------------------------------------------------------------------
template<bool GELU>
__global__ void __launch_bounds__(256, 1)
mma_gemm(const float* __restrict__ A1, const float* __restrict__ A2,
         int K1, int K2,
         const float* __restrict__ W1, const float* __restrict__ W2,
         const float* __restrict__ bias,
         float* __restrict__ C, int M, int N,
         const int* __restrict__ rowA2, const int* __restrict__ cntp)
{
    constexpr int BM = 128, BK = 32, SA = 36;
    const int m0 = blockIdx.x * BM;
    if (cntp) {
        const int mpad = (*cntp + 127) & ~127;
        if (m0 >= mpad) return;
    }

    extern __shared__ uint32_t sm[];
    uint32_t* As = sm;
    uint32_t* Ws = sm + 2 * BM * SA;

    const int K  = K1 + K2;
    const int n0 = blockIdx.y * BM;
    const int tid  = threadIdx.x;
    const int lane = tid & 31;
    const int warp = tid >> 5;
    const int warpM = warp >> 2;
    const int warpN = warp & 3;
    const int lrow = tid >> 3;
    const int lcol = (tid & 7) * 4;

    float4 pa[4], pb[4];
    auto fetch = [&](int k0) {
        const int gk = k0 + lcol;
        #pragma unroll
        for (int p = 0; p < 4; p++) {
            const int r = lrow + p * 32;
            const int m = m0 + r;
            const float* srcA;
            if (gk < K1) {
                srcA = A1 + (size_t)m * K1 + gk;
            } else {
                const int mr = rowA2 ? rowA2[m] : m;
                srcA = A2 + (size_t)mr * K2 + (gk - K1);
            }
            pa[p] = *(const float4*)srcA;
            const int n = n0 + r;
            if (n < N) {
                const float* srcW = (gk < K1)
                    ? W1 + (size_t)n * K1 + gk
                    : W2 + (size_t)n * K2 + (gk - K1);
                pb[p] = *(const float4*)srcW;
            } else {
                pb[p] = make_float4(0.f, 0.f, 0.f, 0.f);
            }
        }
    };
    auto stage = [&](int buf) {
        #pragma unroll
        for (int p = 0; p < 4; p++) {
            const int r = lrow + p * 32;
            uint32_t* da = As + buf * BM * SA + r * SA + lcol;
            da[0] = f2tf32(pa[p].x); da[1] = f2tf32(pa[p].y);
            da[2] = f2tf32(pa[p].z); da[3] = f2tf32(pa[p].w);
            uint32_t* dw = Ws + buf * BM * SA + r * SA + lcol;
            dw[0] = f2tf32(pb[p].x); dw[1] = f2tf32(pb[p].y);
            dw[2] = f2tf32(pb[p].z); dw[3] = f2tf32(pb[p].w);
        }
    };

    float acc[4][4][4] = {};

    const int quad = lane >> 3, qr = lane & 7;
    const int aRowB = warpM * 64 + (quad & 1) * 8 + qr;
    const int aColB = (quad >> 1) * 4;
    const int bq = (lane & 15) >> 3, br = lane & 7;
    const int bRowB = warpN * 32 + br;
    const int bColB = bq * 4;

    const uint32_t smA = (uint32_t)__cvta_generic_to_shared(As);
    const uint32_t smW = (uint32_t)__cvta_generic_to_shared(Ws);

    fetch(0);
    stage(0);
    __syncthreads();

    int buf = 0;
    const int nk = K / BK;
    for (int it = 0; it < nk; it++) {
        if (it + 1 < nk) fetch((it + 1) * BK);

        const uint32_t baseA = smA + (uint32_t)(buf * BM * SA) * 4u;
        const uint32_t baseW = smW + (uint32_t)(buf * BM * SA) * 4u;

        #pragma unroll
        for (int ks = 0; ks < BK / 8; ks++) {
            uint32_t a[4][4], b[4][2];
            #pragma unroll
            for (int mi = 0; mi < 4; mi++) {
                uint32_t ad = baseA + (uint32_t)(((aRowB + mi * 16) * SA) + ks * 8 + aColB) * 4u;
                asm volatile("ldmatrix.sync.aligned.m8n8.x4.shared.b16 {%0,%1,%2,%3}, [%4];\n"
                             : "=r"(a[mi][0]), "=r"(a[mi][1]), "=r"(a[mi][2]), "=r"(a[mi][3])
                             : "r"(ad));
            }
            #pragma unroll
            for (int ni = 0; ni < 4; ni++) {
                uint32_t bd = baseW + (uint32_t)(((bRowB + ni * 8) * SA) + ks * 8 + bColB) * 4u;
                asm volatile("ldmatrix.sync.aligned.m8n8.x2.shared.b16 {%0,%1}, [%2];\n"
                             : "=r"(b[ni][0]), "=r"(b[ni][1])
                             : "r"(bd));
            }
            #pragma unroll
            for (int mi = 0; mi < 4; mi++)
                #pragma unroll
                for (int ni = 0; ni < 4; ni++) {
                    asm volatile(
                        "mma.sync.aligned.m16n8k8.row.col.f32.tf32.tf32.f32 "
                        "{%0,%1,%2,%3}, {%4,%5,%6,%7}, {%8,%9}, {%0,%1,%2,%3};\n"
                        : "+f"(acc[mi][ni][0]), "+f"(acc[mi][ni][1]),
                          "+f"(acc[mi][ni][2]), "+f"(acc[mi][ni][3])
                        : "r"(a[mi][0]), "r"(a[mi][1]), "r"(a[mi][2]), "r"(a[mi][3]),
                          "r"(b[ni][0]), "r"(b[ni][1]));
                }
        }

        if (it + 1 < nk) stage(buf ^ 1);
        __syncthreads();
        buf ^= 1;
    }

    const int g = lane >> 2, l = lane & 3;
    #pragma unroll
    for (int mi = 0; mi < 4; mi++) {
        #pragma unroll
        for (int ni = 0; ni < 4; ni++) {
            const int m = m0 + warpM * 64 + mi * 16 + g;
            const int n = n0 + warpN * 32 + ni * 8 + 2 * l;
            float* c = acc[mi][ni];
            if (n < N) {
                float v0 = c[0] + bias[n];
                float v2 = c[2] + bias[n];
                if (GELU) { v0 = gelu_exact(v0); v2 = gelu_exact(v2); }
                C[(size_t)m * N + n]       = v0;
                C[(size_t)(m + 8) * N + n] = v2;
            }
            if (n + 1 < N) {
                float v1 = c[1] + bias[n + 1];
                float v3 = c[3] + bias[n + 1];
                if (GELU) { v1 = gelu_exact(v1); v3 = gelu_exact(v3); }
                C[(size_t)m * N + n + 1]       = v1;
                C[(size_t)(m + 8) * N + n + 1] = v3;
            }
        }
    }
}

// ---------------------------------------------------------------------------
// 64x64 CTA-tile variant (4 warps of 32x32) for the small GEMMs.
// ---------------------------------------------------------------------------
template<bool GELU>
__global__ void __launch_bounds__(128, 1)
mma_gemm64(const float* __restrict__ A1, const float* __restrict__ A2,
           int K1, int K2,
           const float* __restrict__ W1, const float* __restrict__ W2,
           const float* __restrict__ bias,
           float* __restrict__ C, int M, int N,
           const int* __restrict__ rowA2)
{
    constexpr int BM = 64, BK = 32, SA = 36;
    extern __shared__ uint32_t sm[];
    uint32_t* As = sm;
    uint32_t* Ws = sm + 2 * BM * SA;

    const int K  = K1 + K2;
    const int m0 = blockIdx.x * BM;
    const int n0 = blockIdx.y * BM;
    const int tid  = threadIdx.x;
    const int lane = tid & 31;
    const int warp = tid >> 5;
    const int warpM = warp >> 1;
    const int warpN = warp & 1;
    const int lrow = tid >> 3;
    const int lcol = (tid & 7) * 4;

    float4 pa[4], pb[4];
    auto fetch = [&](int k0) {
        const int gk = k0 + lcol;
        #pragma unroll
        for (int p = 0; p < 4; p++) {
            const int r = lrow + p * 16;
            const int m = m0 + r;
            const float* srcA;
            if (gk < K1) {
                srcA = A1 + (size_t)m * K1 + gk;
            } else {
                const int mr = rowA2 ? rowA2[m] : m;
                srcA = A2 + (size_t)mr * K2 + (gk - K1);
            }
            pa[p] = *(const float4*)srcA;
            const int n = n0 + r;
            if (n < N) {
                const float* srcW = (gk < K1)
                    ? W1 + (size_t)n * K1 + gk
                    : W2 + (size_t)n * K2 + (gk - K1);
                pb[p] = *(const float4*)srcW;
            } else {
                pb[p] = make_float4(0.f, 0.f, 0.f, 0.f);
            }
        }
    };
    auto stage = [&](int buf) {
        #pragma unroll
        for (int p = 0; p < 4; p++) {
            const int r = lrow + p * 16;
            uint32_t* da = As + buf * BM * SA + r * SA + lcol;
            da[0] = f2tf32(pa[p].x); da[1] = f2tf32(pa[p].y);
            da[2] = f2tf32(pa[p].z); da[3] = f2tf32(pa[p].w);
            uint32_t* dw = Ws + buf * BM * SA + r * SA + lcol;
            dw[0] = f2tf32(pb[p].x); dw[1] = f2tf32(pb[p].y);
            dw[2] = f2tf32(pb[p].z); dw[3] = f2tf32(pb[p].w);
        }
    };

    float acc[2][4][4] = {};

    const int quad = lane >> 3, qr = lane & 7;
    const int aRowB = warpM * 32 + (quad & 1) * 8 + qr;
    const int aColB = (quad >> 1) * 4;
    const int bq = (lane & 15) >> 3, br = lane & 7;
    const int bRowB = warpN * 32 + br;
    const int bColB = bq * 4;

    const uint32_t smA = (uint32_t)__cvta_generic_to_shared(As);
    const uint32_t smW = (uint32_t)__cvta_generic_to_shared(Ws);

    fetch(0);
    stage(0);
    __syncthreads();

    int buf = 0;
    const int nk = K / BK;
    for (int it = 0; it < nk; it++) {
        if (it + 1 < nk) fetch((it + 1) * BK);

        const uint32_t baseA = smA + (uint32_t)(buf * BM * SA) * 4u;
        const uint32_t baseW = smW + (uint32_t)(buf * BM * SA) * 4u;

        #pragma unroll
        for (int ks = 0; ks < BK / 8; ks++) {
            uint32_t a[2][4], b[4][2];
            #pragma unroll
            for (int mi = 0; mi < 2; mi++) {
                uint32_t ad = baseA + (uint32_t)(((aRowB + mi * 16) * SA) + ks * 8 + aColB) * 4u;
                asm volatile("ldmatrix.sync.aligned.m8n8.x4.shared.b16 {%0,%1,%2,%3}, [%4];\n"
                             : "=r"(a[mi][0]), "=r"(a[mi][1]), "=r"(a[mi][2]), "=r"(a[mi][3])
                             : "r"(ad));
            }
            #pragma unroll
            for (int ni = 0; ni < 4; ni++) {
                uint32_t bd = baseW + (uint32_t)(((bRowB + ni * 8) * SA) + ks * 8 + bColB) * 4u;
                asm volatile("ldmatrix.sync.aligned.m8n8.x2.shared.b16 {%0,%1}, [%2];\n"
                             : "=r"(b[ni][0]), "=r"(b[ni][1])
                             : "r"(bd));
            }
            #pragma unroll
            for (int mi = 0; mi < 2; mi++)
                #pragma unroll
                for (int ni = 0; ni < 4; ni++) {
                    asm volatile(
                        "mma.sync.aligned.m16n8k8.row.col.f32.tf32.tf32.f32 "
                        "{%0,%1,%2,%3}, {%4,%5,%6,%7}, {%8,%9}, {%0,%1,%2,%3};\n"
                        : "+f"(acc[mi][ni][0]), "+f"(acc[mi][ni][1]),
                          "+f"(acc[mi][ni][2]), "+f"(acc[mi][ni][3])
                        : "r"(a[mi][0]), "r"(a[mi][1]), "r"(a[mi][2]), "r"(a[mi][3]),
                          "r"(b[ni][0]), "r"(b[ni][1]));
                }
        }

        if (it + 1 < nk) stage(buf ^ 1);
        __syncthreads();
        buf ^= 1;
    }

    const int g = lane >> 2, l = lane & 3;
    #pragma unroll
    for (int mi = 0; mi < 2; mi++) {
        #pragma unroll
        for (int ni = 0; ni < 4; ni++) {
            const int m = m0 + warpM * 32 + mi * 16 + g;
            const int n = n0 + warpN * 32 + ni * 8 + 2 * l;
            float* c = acc[mi][ni];
            if (n < N) {
                float v0 = c[0] + bias[n];
                float v2 = c[2] + bias[n];
                if (GELU) { v0 = gelu_exact(v0); v2 = gelu_exact(v2); }
                C[(size_t)m * N + n]       = v0;
                C[(size_t)(m + 8) * N + n] = v2;
            }
            if (n + 1 < N) {
                float v1 = c[1] + bias[n + 1];
                float v3 = c[3] + bias[n + 1];
                if (GELU) { v1 = gelu_exact(v1); v3 = gelu_exact(v3); }
                C[(size_t)m * N + n + 1]       = v1;
                C[(size_t)(m + 8) * N + n + 1] = v3;
            }
        }
    }
}

// ---------------------------------------------------------------------------
// Launch
// ---------------------------------------------------------------------------
extern "C" void kernel_launch(void* const* d_in, const int* in_sizes, int n_in,
                              void* d_out, int out_size)
{
    const float* x    = (const float*)d_in[0];
    const int*   idx0 = (const int*)  d_in[1];
    const int*   idx1 = (const int*)  d_in[3];
    const float* Wl0  = (const float*)d_in[5];
    const float* bl0  = (const float*)d_in[6];
    const float* Wr0  = (const float*)d_in[7];
    const float* Wl1  = (const float*)d_in[8];
    const float* bl1  = (const float*)d_in[9];
    const float* Wr1  = (const float*)d_in[10];
    const float* Wo   = (const float*)d_in[11];
    const float* bo   = (const float*)d_in[12];
    float* out = (float*)d_out;

    float *agg0, *h0, *agg1, *h1;
    int *mask, *list, *remap, *cnt;
    cudaGetSymbolAddress((void**)&agg0,  g_agg0);
    cudaGetSymbolAddress((void**)&h0,    g_h0);
    cudaGetSymbolAddress((void**)&agg1,  g_agg1);
    cudaGetSymbolAddress((void**)&h1,    g_h1);
    cudaGetSymbolAddress((void**)&mask,  g_mask);
    cudaGetSymbolAddress((void**)&list,  g_list);
    cudaGetSymbolAddress((void**)&remap, g_remap);
    cudaGetSymbolAddress((void**)&cnt,   g_cnt);

    const int SMEM_G128 = 4 * 128 * 36 * 4;          // 73728 B
    const int SMEM_G64  = 4 * 64 * 36 * 4;           // 36864 B
    const int SMEM_A0   = 8 * DEG0c * DINc * 4;      // 65536 B
    const int SMEM_A1   = 4 * DEG1c * DHc * 4;       // 40960 B
    cudaFuncSetAttribute(mma_gemm<true>,    cudaFuncAttributeMaxDynamicSharedMemorySize, SMEM_G128);
    cudaFuncSetAttribute(mma_gemm64<true>,  cudaFuncAttributeMaxDynamicSharedMemorySize, SMEM_G64);
    cudaFuncSetAttribute(mma_gemm64<false>, cudaFuncAttributeMaxDynamicSharedMemorySize, SMEM_G64);
    cudaFuncSetAttribute(agg_cp_kernel<DINc, DEG0c, 8, true,  false>,
                         cudaFuncAttributeMaxDynamicSharedMemorySize, SMEM_A0);
    cudaFuncSetAttribute(agg_cp_kernel<DHc,  DEG1c, 4, false, true>,
                         cudaFuncAttributeMaxDynamicSharedMemorySize, SMEM_A1);

    // Dedup: mark nodes needed by layer 1, build compact list + remap
    init_kernel<<<N1c / 256, 256>>>(mask, list, cnt);
    mark_kernel<<<(E1c + 255) / 256, 256>>>(idx1, mask);
    compact_kernel<<<N1c / 256, 256>>>(mask, list, remap, cnt);

    // Layer 0 (compact rows only): mean over 16 neighbors (D=128)
    agg_cp_kernel<DINc, DEG0c, 8, true, false>
        <<<N1c / 8, 256, SMEM_A0>>>(x, idx0, agg0, list, nullptr, cnt);

    // Layer 0 GEMM (compact rows): h0c = gelu([agg0c | x[list]] @ [Wl0|Wr0]^T + bl0)
    mma_gemm<true><<<dim3(N1c / 128, DHc / 128), 256, SMEM_G128>>>(
        agg0, x, DINc, DINc, Wl0, Wr0, bl0, h0, N1c, DHc, list, cnt);

    // Layer 1: mean over 10 neighbors (D=256), srcs remapped into compact h0
    agg_cp_kernel<DHc, DEG1c, 4, false, true>
        <<<N2c / 4, 256, SMEM_A1>>>(h0, idx1, agg1, nullptr, remap, nullptr);

    // Layer 1 GEMM: h1 = gelu([agg1 | h0c[remap]] @ [Wl1|Wr1]^T + bl1)  [4096 x 256]
    mma_gemm64<true><<<dim3(N2c / 64, DHc / 64), 128, SMEM_G64>>>(
        agg1, h0, DHc, DHc, Wl1, Wr1, bl1, h1, N2c, DHc, remap);

    // Output projection: out = h1 @ Wo^T + bo   [4096 x 47]
    mma_gemm64<false><<<dim3(N2c / 64, 1), 128, SMEM_G64>>>(
        h1, h1, DHc, 0, Wo, Wo, bo, out, N2c, DOUTc, nullptr);
}